// round 16
// baseline (speedup 1.0000x reference)
#include <cuda_runtime.h>

#define BATCH 32
#define LSEQ  2048
#define DDIM  1024
#define NVOC  320
#define SPLIT 32
#define LSEG  (LSEQ / SPLIT)   // 64
#define WTH   512              // weights kernel threads
#define GTH   256              // gemv kernel threads

// Scratch (allocation-free rule: __device__ globals)
__device__ float g_w[BATCH * LSEQ];   // unnormalized p
__device__ float g_sum[BATCH];        // per-batch sum of p

// ---------------------------------------------------------------------------
// Kernel 1: per-batch unnormalized weights + sum. 32 blocks x 512 thr.
// Triggers programmatic launch completion at entry so the GEMV kernel's
// blocks start (and prefetch) while this runs.
// vq_indices / input_lengths are int32 (JAX x64 downcast).
// ---------------------------------------------------------------------------
#define WJ (LSEQ / WTH)   // 4 positions per thread

__global__ void __launch_bounds__(WTH)
weights_kernel(const int* __restrict__ lengths,
               const int* __restrict__ vq)
{
    cudaTriggerProgrammaticLaunchCompletion();

    __shared__ int   s_cx[NVOC];
    __shared__ int   s_cy[NVOC];
    __shared__ float s_red[WTH / 32];

    const int b   = blockIdx.x;
    const int tid = threadIdx.x;

    if (tid < NVOC) { s_cx[tid] = 0; s_cy[tid] = 0; }   // WTH=512 > NVOC=320
    __syncthreads();

    const int4* vq4 = reinterpret_cast<const int4*>(vq) + (size_t)b * (LSEQ / 2);
    int4 vr[WJ / 2];
#pragma unroll
    for (int j = 0; j < WJ / 2; j++)
        vr[j] = vq4[tid + j * WTH];
#pragma unroll
    for (int j = 0; j < WJ / 2; j++) {
        atomicAdd(&s_cx[vr[j].x], 1);
        atomicAdd(&s_cy[vr[j].y], 1);
        atomicAdd(&s_cx[vr[j].z], 1);
        atomicAdd(&s_cy[vr[j].w], 1);
    }
    __syncthreads();

    const int len = lengths[b];
    float lsum = 0.0f;
#pragma unroll
    for (int j = 0; j < WJ / 2; j++) {
        const int l0 = 2 * (tid + j * WTH);
        float p0 = 0.0f, p1 = 0.0f;
        if (l0 < len)
            p0 = __fdividef(1.0f, (float)(s_cx[vr[j].x] + s_cy[vr[j].y]));
        if (l0 + 1 < len)
            p1 = __fdividef(1.0f, (float)(s_cx[vr[j].z] + s_cy[vr[j].w]));
        g_w[(size_t)b * LSEQ + l0]     = p0;
        g_w[(size_t)b * LSEQ + l0 + 1] = p1;
        lsum += p0 + p1;
    }

#pragma unroll
    for (int o = 16; o > 0; o >>= 1) lsum += __shfl_xor_sync(0xffffffffu, lsum, o);
    if ((tid & 31) == 0) s_red[tid >> 5] = lsum;
    __syncthreads();
    if (tid < WTH / 32) {
        float s = s_red[tid];
#pragma unroll
        for (int o = 8; o > 0; o >>= 1) s += __shfl_xor_sync(0xffffu, s, o);
        if (tid == 0) g_sum[b] = s;
    }
}

// ---------------------------------------------------------------------------
// Kernel 2: prologue-free streaming GEMV. grid (BATCH, SPLIT) b-fastest,
// 256 thr, 64-row segments. Prefetches feat (independent of kernel 1),
// then griddepsync, loads its 64 weights + 1/sum, streams, red.global.
// ---------------------------------------------------------------------------
#define PF_LINES 3   // 3 x 128B lines/thread = 24 of 64 rows

__global__ void __launch_bounds__(GTH)
gemv_kernel(const float* __restrict__ feat,
            const int*   __restrict__ lengths,
            float*       __restrict__ out)
{
    __shared__ float s_w[LSEG];
    __shared__ float s_inv;

    const int b     = blockIdx.x;   // 0..BATCH-1 (fastest)
    const int split = blockIdx.y;   // 0..SPLIT-1
    const int tid   = threadIdx.x;  // 0..255

    const int len       = lengths[b];          // input: safe pre-sync
    const int seg_start = split * LSEG;
    if (seg_start >= len) return;              // dead segment: exit pre-sync
    const int rows_eff  = min(LSEG, len - seg_start);

    // Segment base: input_feature[b, 1, seg_start, :]  (N=2, take last)
    const float* seg = feat + ((size_t)b * 2 + 1) * (size_t)LSEQ * DDIM
                            + (size_t)seg_start * DDIM;

    // Prefetch leading live rows while the weights kernel still runs.
    {
        const size_t live_bytes = (size_t)rows_eff * DDIM * 4;
        const char*  base = reinterpret_cast<const char*>(seg);
#pragma unroll
        for (int i = 0; i < PF_LINES; i++) {
            const size_t off = ((size_t)tid + (size_t)i * GTH) * 128;
            if (off < live_bytes)
                asm volatile("prefetch.global.L2 [%0];"
                             :: "l"(base + off) : "memory");
        }
    }

    // Wait for weights kernel completion (PDL).
    cudaGridDependencySynchronize();

    if (tid < LSEG)
        s_w[tid] = g_w[(size_t)b * LSEQ + seg_start + tid];
    if (tid == 0)
        s_inv = __fdividef(1.0f, g_sum[b]);
    __syncthreads();

    const float4* f4 = reinterpret_cast<const float4*>(seg) + tid;

    float4 acc = make_float4(0.f, 0.f, 0.f, 0.f);
#pragma unroll 16
    for (int l = 0; l < rows_eff; l++) {
        const float  w = s_w[l];
        const float4 v = __ldcs(f4 + (size_t)l * (DDIM / 4));
        acc.x = fmaf(w, v.x, acc.x);
        acc.y = fmaf(w, v.y, acc.y);
        acc.z = fmaf(w, v.z, acc.z);
        acc.w = fmaf(w, v.w, acc.w);
    }

    const float inv = s_inv;
    acc.x *= inv; acc.y *= inv; acc.z *= inv; acc.w *= inv;

    float* dst = out + (size_t)b * DDIM + tid * 4;
    asm volatile("red.global.add.v4.f32 [%0], {%1, %2, %3, %4};"
                 :: "l"(dst), "f"(acc.x), "f"(acc.y), "f"(acc.z), "f"(acc.w)
                 : "memory");
}

// ---------------------------------------------------------------------------
extern "C" void kernel_launch(void* const* d_in, const int* in_sizes, int n_in,
                              void* d_out, int out_size)
{
    const float* feat    = (const float*)d_in[0];
    const int*   lengths = (const int*)d_in[1];
    const int*   vq      = (const int*)d_in[2];
    float*       out     = (float*)d_out;

    (void)in_sizes; (void)n_in;

    // Output is poisoned before timing and accumulated via atomics: zero it.
    cudaMemsetAsync(out, 0, (size_t)out_size * sizeof(float));

    weights_kernel<<<BATCH, WTH>>>(lengths, vq);

    // GEMV with programmatic stream serialization: blocks launch while the
    // weights kernel runs; griddepsync provides the ordering.
    cudaLaunchConfig_t cfg = {};
    cfg.gridDim  = dim3(BATCH, SPLIT);
    cfg.blockDim = dim3(GTH);
    cudaLaunchAttribute attr[1];
    attr[0].id = cudaLaunchAttributeProgrammaticStreamSerialization;
    attr[0].val.programmaticStreamSerializationAllowed = 1;
    cfg.attrs    = attr;
    cfg.numAttrs = 1;
    cudaLaunchKernelEx(&cfg, gemv_kernel, feat, lengths, out);
}

// round 17
// speedup vs baseline: 1.0462x; 1.0462x over previous
#include <cuda_runtime.h>

#define BATCH 32
#define LSEQ  2048
#define DDIM  1024
#define NVOC  320
#define SPLIT 16
#define NTHR  512

// ---------------------------------------------------------------------------
// R17: R12 fused body + proportional row partition.
// Block (split,b) streams live rows [split*len/16, (split+1)*len/16) of
// batch b: every block is live, work proportional to len_b (64..128 rows),
// so per-SM load equalizes (R16 showed dead-block imbalance, not the
// prologue, was the ~6us gap above the traffic floor).
// Redundant per-block histogram+weights as in R12 (known-hidden cost).
// vq_indices / input_lengths are int32 (JAX x64 downcast).
// ---------------------------------------------------------------------------
#define JL       (LSEQ / NTHR)  // 4 positions per thread
#define PF_LINES 3

__global__ void __launch_bounds__(NTHR)
gemv_fused_kernel(const float* __restrict__ feat,
                  const int*   __restrict__ lengths,
                  const int*   __restrict__ vq,
                  float*       __restrict__ out)
{
    __shared__ int   s_cx[NVOC];
    __shared__ int   s_cy[NVOC];
    __shared__ float s_p[LSEQ];     // unnormalized per-position weights
    __shared__ float s_red[NTHR / 32];
    __shared__ float s_inv;

    const int b     = blockIdx.x;   // 0..BATCH-1 (fastest: mixes batches per SM)
    const int split = blockIdx.y;   // 0..SPLIT-1
    const int tid   = threadIdx.x;  // 0..511

    // Proportional live-row partition: all blocks live, 64..128 rows each.
    const int len       = lengths[b];
    const int seg_start = (split * len) >> 4;          // split*len/16
    const int seg_end   = ((split + 1) * len) >> 4;
    const int rows_eff  = seg_end - seg_start;

    // Segment base: input_feature[b, 1, seg_start, :]  (N=2, take last)
    const float* seg = feat + ((size_t)b * 2 + 1) * (size_t)LSEQ * DDIM
                            + (size_t)seg_start * DDIM;

    // ---- Phase 0: L2 prefetch of leading live rows -------------------------
    {
        const size_t live_bytes = (size_t)rows_eff * DDIM * 4;
        const char*  base = reinterpret_cast<const char*>(seg);
#pragma unroll
        for (int i = 0; i < PF_LINES; i++) {
            const size_t off = ((size_t)tid + (size_t)i * NTHR) * 128;
            if (off < live_bytes)
                asm volatile("prefetch.global.L2 [%0];"
                             :: "l"(base + off) : "memory");
        }
    }

    // ---- Hoisted vq loads (int4: two (x,y) pairs per 16B) ------------------
    const int4* vq4 = reinterpret_cast<const int4*>(vq) + (size_t)b * (LSEQ / 2);
    int4 vr[JL / 2];
#pragma unroll
    for (int j = 0; j < JL / 2; j++)
        vr[j] = vq4[tid + j * NTHR];

    // ---- Phase A: histogram over ALL positions (reference is unmasked) ----
    if (tid < NVOC) { s_cx[tid] = 0; s_cy[tid] = 0; }   // NTHR=512 > NVOC=320
    __syncthreads();

#pragma unroll
    for (int j = 0; j < JL / 2; j++) {
        atomicAdd(&s_cx[vr[j].x], 1);
        atomicAdd(&s_cy[vr[j].y], 1);
        atomicAdd(&s_cx[vr[j].z], 1);
        atomicAdd(&s_cy[vr[j].w], 1);
    }
    __syncthreads();

    // ---- Phase B: per-position p = mask / freq, block sum -> 1/sum --------
    float lsum = 0.0f;
#pragma unroll
    for (int j = 0; j < JL / 2; j++) {
        const int l0 = 2 * (tid + j * NTHR);
        float p0 = 0.0f, p1 = 0.0f;
        if (l0 < len)
            p0 = __fdividef(1.0f, (float)(s_cx[vr[j].x] + s_cy[vr[j].y]));
        if (l0 + 1 < len)
            p1 = __fdividef(1.0f, (float)(s_cx[vr[j].z] + s_cy[vr[j].w]));
        s_p[l0]     = p0;
        s_p[l0 + 1] = p1;
        lsum += p0 + p1;
    }
#pragma unroll
    for (int o = 16; o > 0; o >>= 1) lsum += __shfl_xor_sync(0xffffffffu, lsum, o);
    if ((tid & 31) == 0) s_red[tid >> 5] = lsum;
    __syncthreads();
    if (tid < NTHR / 32) {   // 16 partials
        float s = s_red[tid];
#pragma unroll
        for (int o = 8; o > 0; o >>= 1) s += __shfl_xor_sync(0xffffu, s, o);
        if (tid == 0) s_inv = __fdividef(1.0f, s);
    }
    __syncthreads();

    // ---- Phase C: stream live rows, two thread-halves interleaved by parity
    const int dlane = tid & 255;
    const int half  = tid >> 8;

    const float4* f4 = reinterpret_cast<const float4*>(seg)
                       + (size_t)half * (DDIM / 4) + dlane;
    const float*  pw = &s_p[seg_start + half];

    float4 acc = make_float4(0.f, 0.f, 0.f, 0.f);
#pragma unroll 8
    for (int l = half; l < rows_eff; l += 2) {
        const float  w = pw[l - half];
        const float4 v = __ldcs(f4 + (size_t)(l - half) * (DDIM / 4));
        acc.x = fmaf(w, v.x, acc.x);
        acc.y = fmaf(w, v.y, acc.y);
        acc.z = fmaf(w, v.z, acc.z);
        acc.w = fmaf(w, v.w, acc.w);
    }

    const float inv = s_inv;
    acc.x *= inv; acc.y *= inv; acc.z *= inv; acc.w *= inv;

    // ---- Phase D: vector reduction straight into the output ----------------
    float* dst = out + (size_t)b * DDIM + dlane * 4;
    asm volatile("red.global.add.v4.f32 [%0], {%1, %2, %3, %4};"
                 :: "l"(dst), "f"(acc.x), "f"(acc.y), "f"(acc.z), "f"(acc.w)
                 : "memory");
}

// ---------------------------------------------------------------------------
extern "C" void kernel_launch(void* const* d_in, const int* in_sizes, int n_in,
                              void* d_out, int out_size)
{
    const float* feat    = (const float*)d_in[0];
    const int*   lengths = (const int*)d_in[1];
    const int*   vq      = (const int*)d_in[2];
    float*       out     = (float*)d_out;

    (void)in_sizes; (void)n_in;

    // Output is poisoned before timing and accumulated via atomics: zero it.
    cudaMemsetAsync(out, 0, (size_t)out_size * sizeof(float));
    gemv_fused_kernel<<<dim3(BATCH, SPLIT), NTHR>>>(feat, lengths, vq, out);
}